// round 7
// baseline (speedup 1.0000x reference)
#include <cuda_runtime.h>

#define BB 512
#define TT 128
#define FF 256
#define HH 384
#define LL 3
#define KW 10
#define LAB 25
#define GATES 1542
#define HID 64
#define CONVK (HH * KW)   // 3840
#define NPAD 1664         // 13*128, 26*64
#define NSTEP_TILES 25    // 25*64 = 1600 >= GATES
#define GRIDP 148         // persistent grid (<= SM count, co-residency guaranteed)

// ---------------- device scratch ----------------
__device__ __align__(16) int   g_perm[BB];
__device__ __align__(16) int   g_vlen[BB];
__device__ __align__(16) int   g_nact[TT];
__device__ float g_pre[(size_t)TT * BB * NPAD];               // 436 MB
__device__ float g_xo[BB * NPAD];
__device__ __align__(16) float g_h[BB * HH];
__device__ __align__(16) float g_c[BB * HH];
__device__ __align__(16) float g_hist[(size_t)TT * BB * HH];  // 100 MB
__device__ __align__(16) float g_dish[TT * BB];
__device__ __align__(16) float g_convT[CONVK * HH];
__device__ __align__(16) float g_lh[BB * CONVK];
__device__ __align__(16) float g_theme[BB * HH];
__device__ __align__(16) float g_conv[BB * HH];
// tf32 split weights, transposed to [n][k]
__device__ __align__(16) float g_BkwT[2][NPAD * FF];          // hi, lo
__device__ __align__(16) float g_BrwT[2][NPAD * HH];
__device__ __align__(16) float g_bias0[NPAD];
__device__ __align__(16) float g_biasT[NPAD];
// grid barrier state
__device__ unsigned g_ctr;
__device__ unsigned g_phase;

__device__ __forceinline__ float sigm(float x) { return 1.f / (1.f + expf(-x)); }

__device__ __forceinline__ float tf32r(float x) {
    unsigned u;
    asm("cvt.rna.tf32.f32 %0, %1;" : "=r"(u) : "f"(x));
    return __uint_as_float(u);
}

#define MMA_TF32(cc, a, b0, b1)                                                 \
    asm volatile("mma.sync.aligned.m16n8k8.row.col.f32.tf32.tf32.f32 "          \
        "{%0,%1,%2,%3}, {%4,%5,%6,%7}, {%8,%9}, {%0,%1,%2,%3};"                 \
        : "+f"((cc)[0]), "+f"((cc)[1]), "+f"((cc)[2]), "+f"((cc)[3])            \
        : "r"(__float_as_uint((a)[0])), "r"(__float_as_uint((a)[1])),           \
          "r"(__float_as_uint((a)[2])), "r"(__float_as_uint((a)[3])),           \
          "r"(__float_as_uint(b0)), "r"(__float_as_uint(b1)))

// ---------------- setup ----------------
__global__ void k_setup(const int* __restrict__ vlen) {
    int cnt[129];
    for (int v = 0; v <= 128; v++) cnt[v] = 0;
    for (int b = 0; b < BB; b++) cnt[vlen[b]]++;
    int cur[129];
    int off = 0;
    for (int v = 128; v >= 1; v--) { cur[v] = off; off += cnt[v]; }
    for (int b = 0; b < BB; b++) {
        int v = vlen[b];
        int p = cur[v]++;
        g_perm[p] = b;
        g_vlen[p] = v;
    }
    int suf = 0;
    for (int t = TT - 1; t >= 0; t--) { suf += cnt[t + 1]; g_nact[t] = suf; }
    g_ctr = 0;
    g_phase = 0;
}

__global__ void k_zero() {
    int i = blockIdx.x * blockDim.x + threadIdx.x;
    if (i < BB * HH) { g_h[i] = 0.f; g_c[i] = 0.f; }
}

__global__ void k_convT(const float* __restrict__ cw) {
    int i = blockIdx.x * blockDim.x + threadIdx.x;
    if (i >= HH * HH * KW) return;
    int k  = i % KW;
    int hh = (i / KW) % HH;
    int o  = i / (KW * HH);
    g_convT[(hh * KW + k) * HH + o] = cw[i];
}

// ---------------- prep: split+transpose weights, biases ----------------
__global__ void k_prep(const float* __restrict__ kw, const float* __restrict__ kb,
                       const float* __restrict__ rw, const float* __restrict__ rb) {
    int n = blockIdx.x;
    int k = threadIdx.x;
    bool v = n < GATES;
    if (k < FF) {
        float w = v ? kw[k * GATES + n] : 0.f;
        float hi = tf32r(w);
        g_BkwT[0][n * FF + k] = hi;
        g_BkwT[1][n * FF + k] = w - hi;
    }
    if (k < HH) {
        float w = v ? rw[k * GATES + n] : 0.f;
        float hi = tf32r(w);
        g_BrwT[0][n * HH + k] = hi;
        g_BrwT[1][n * HH + k] = w - hi;
    }
    if (k == 0) {
        float b0 = v ? (kb[n] + rb[n]) : 0.f;
        float bT = b0 + (v ? (kw[FF * GATES + n] + rw[HH * GATES + n]) : 0.f);
        g_bias0[n] = b0;
        g_biasT[n] = bT;
    }
}

// ---------------- tf32 pre-GEMM: 64(t) x 128(n) tiles, vlen skip ----------------
// grid (13, 1024): p = by>>1, t0 = (by&1)*64. 256 thr, 8 warps (2wm x 4wn), warp 32x32.
__global__ __launch_bounds__(256) void k_gemm_pre_tf32(const float* __restrict__ X) {
    __shared__ float SA[2][64 * 20];    // [hi/lo]
    __shared__ float SB[2][128 * 20];

    int p  = blockIdx.y >> 1;
    int t0 = (blockIdx.y & 1) * 64;
    if (t0 >= g_vlen[p]) return;
    int n0 = blockIdx.x * 128;
    int tid = threadIdx.x;
    int lane = tid & 31, wid = tid >> 5;
    int wm = wid >> 2, wn = wid & 3;
    int g = lane >> 2, tq = lane & 3;
    const float* A = X + (size_t)g_perm[p] * (TT * FF) + (size_t)t0 * FF;

    int am = tid >> 2, ak = (tid & 3) * 4;   // A: 64 rows x 16, float4 each
    int bm = tid >> 1, bk = (tid & 1) * 8;   // B: 128 rows x 16, 2x float4

    float c[2][4][4] = {};

    float4 va;
    float4 vb[2][2];
    va = *(const float4*)(A + am * FF + ak);
    #pragma unroll
    for (int h = 0; h < 2; h++) {
        vb[h][0] = *(const float4*)(&g_BkwT[h][(n0 + bm) * FF + bk]);
        vb[h][1] = *(const float4*)(&g_BkwT[h][(n0 + bm) * FF + bk + 4]);
    }

    const int nK = FF / 16;  // 16
    for (int kt = 0; kt < nK; kt++) {
        {
            float4 h4, l4;
            h4.x = tf32r(va.x); l4.x = va.x - h4.x;
            h4.y = tf32r(va.y); l4.y = va.y - h4.y;
            h4.z = tf32r(va.z); l4.z = va.z - h4.z;
            h4.w = tf32r(va.w); l4.w = va.w - h4.w;
            *(float4*)(&SA[0][am * 20 + ak]) = h4;
            *(float4*)(&SA[1][am * 20 + ak]) = l4;
            *(float4*)(&SB[0][bm * 20 + bk]) = vb[0][0];
            *(float4*)(&SB[0][bm * 20 + bk + 4]) = vb[0][1];
            *(float4*)(&SB[1][bm * 20 + bk]) = vb[1][0];
            *(float4*)(&SB[1][bm * 20 + bk + 4]) = vb[1][1];
        }
        __syncthreads();
        if (kt + 1 < nK) {
            int k0 = (kt + 1) * 16;
            va = *(const float4*)(A + am * FF + k0 + ak);
            #pragma unroll
            for (int h = 0; h < 2; h++) {
                vb[h][0] = *(const float4*)(&g_BkwT[h][(n0 + bm) * FF + k0 + bk]);
                vb[h][1] = *(const float4*)(&g_BkwT[h][(n0 + bm) * FF + k0 + bk + 4]);
            }
        }
        #pragma unroll
        for (int k8 = 0; k8 < 2; k8++) {
            int kc = k8 * 8 + tq;
            float ah[2][4], al[2][4];
            #pragma unroll
            for (int mf = 0; mf < 2; mf++) {
                int r = wm * 32 + mf * 16 + g;
                const float* pa = &SA[0][r * 20 + kc];
                ah[mf][0] = pa[0];   ah[mf][1] = pa[160];
                ah[mf][2] = pa[4];   ah[mf][3] = pa[164];
                const float* pl = &SA[1][r * 20 + kc];
                al[mf][0] = pl[0];   al[mf][1] = pl[160];
                al[mf][2] = pl[4];   al[mf][3] = pl[164];
            }
            #pragma unroll
            for (int nf = 0; nf < 4; nf++) {
                int nn = wn * 32 + nf * 8 + g;
                const float* pb = &SB[0][nn * 20 + kc];
                float bh0 = pb[0], bh1 = pb[4];
                const float* pbl = &SB[1][nn * 20 + kc];
                float bl0 = pbl[0], bl1 = pbl[4];
                #pragma unroll
                for (int mf = 0; mf < 2; mf++) {
                    MMA_TF32(c[mf][nf], ah[mf], bh0, bh1);
                    MMA_TF32(c[mf][nf], ah[mf], bl0, bl1);
                    MMA_TF32(c[mf][nf], al[mf], bh0, bh1);
                }
            }
        }
        __syncthreads();
    }

    // epilogue: rows are t = t0 + r
    #pragma unroll
    for (int mf = 0; mf < 2; mf++) {
        int r0 = wm * 32 + mf * 16 + g;
        int r1 = r0 + 8;
        int ta = t0 + r0, tb = t0 + r1;
        #pragma unroll
        for (int nf = 0; nf < 4; nf++) {
            int col = n0 + wn * 32 + nf * 8 + 2 * tq;
            float b0a = (ta == 0) ? g_bias0[col] : g_biasT[col];
            float b0b = (ta == 0) ? g_bias0[col + 1] : g_biasT[col + 1];
            float2 v;
            v.x = c[mf][nf][0] + b0a;
            v.y = c[mf][nf][1] + b0b;
            *(float2*)&g_pre[((size_t)ta * BB + p) * NPAD + col] = v;
            v.x = c[mf][nf][2] + g_biasT[col];
            v.y = c[mf][nf][3] + g_biasT[col + 1];
            *(float2*)&g_pre[((size_t)tb * BB + p) * NPAD + col] = v;
        }
    }
}

// ---------------- grid barrier (persistent kernel; grid <= SM count) ----------------
__device__ __forceinline__ void gsync(unsigned target) {
    __syncthreads();
    if (threadIdx.x == 0) {
        __threadfence();
        if (atomicAdd(&g_ctr, 1u) == GRIDP - 1) {
            atomicExch(&g_ctr, 0u);
            __threadfence();
            atomicExch(&g_phase, target);
        } else {
            while (atomicAdd(&g_phase, 0u) < target) { }
        }
        __threadfence();
    }
    __syncthreads();
}

// ---------------- persistent time loop ----------------
// 148 blocks x 256 thr. Phase A: 64x64 tf32 GEMM tiles; Phase B: pointwise.
__global__ __launch_bounds__(256) void k_loop() {
    __shared__ float SA[2][64 * 20];
    __shared__ float SB[2][64 * 20];
    __shared__ float s_fm[LL], s_im[LL];

    int tid = threadIdx.x;
    int lane = tid & 31, wid = tid >> 5;
    int wm = wid >> 1, wn = wid & 1;      // 4 x 2 warps, warp tile 16 x 32
    int g = lane >> 2, tq = lane & 3;
    int am = tid >> 2, ak = (tid & 3) * 4;  // 64 rows x 16 floats, float4 per thread

    unsigned phase = 0;

    for (int t = 0; t < TT; t++) {
        int na = g_nact[t];
        int mt = (na + 63) >> 6;
        int ntile = mt * NSTEP_TILES;

        // ---- phase A: xo = h @ rec_w + PRE[t] ----
        for (int idx = blockIdx.x; idx < ntile; idx += GRIDP) {
            int m0 = (idx / NSTEP_TILES) * 64;
            int n0 = (idx % NSTEP_TILES) * 64;
            const float* A = g_h + m0 * HH;

            float c[4][4] = {};

            float4 va;
            float4 vb[2];
            va = *(const float4*)(A + am * HH + ak);
            vb[0] = *(const float4*)(&g_BrwT[0][(n0 + am) * HH + ak]);
            vb[1] = *(const float4*)(&g_BrwT[1][(n0 + am) * HH + ak]);

            const int nK = HH / 16;  // 24
            for (int kt = 0; kt < nK; kt++) {
                {
                    float4 h4, l4;
                    h4.x = tf32r(va.x); l4.x = va.x - h4.x;
                    h4.y = tf32r(va.y); l4.y = va.y - h4.y;
                    h4.z = tf32r(va.z); l4.z = va.z - h4.z;
                    h4.w = tf32r(va.w); l4.w = va.w - h4.w;
                    *(float4*)(&SA[0][am * 20 + ak]) = h4;
                    *(float4*)(&SA[1][am * 20 + ak]) = l4;
                    *(float4*)(&SB[0][am * 20 + ak]) = vb[0];
                    *(float4*)(&SB[1][am * 20 + ak]) = vb[1];
                }
                __syncthreads();
                if (kt + 1 < nK) {
                    int k0 = (kt + 1) * 16;
                    va = *(const float4*)(A + am * HH + k0 + ak);
                    vb[0] = *(const float4*)(&g_BrwT[0][(n0 + am) * HH + k0 + ak]);
                    vb[1] = *(const float4*)(&g_BrwT[1][(n0 + am) * HH + k0 + ak]);
                }
                #pragma unroll
                for (int k8 = 0; k8 < 2; k8++) {
                    int kc = k8 * 8 + tq;
                    int r = wm * 16 + g;
                    const float* pa = &SA[0][r * 20 + kc];
                    float ah[4] = { pa[0], pa[160], pa[4], pa[164] };
                    const float* pl = &SA[1][r * 20 + kc];
                    float al[4] = { pl[0], pl[160], pl[4], pl[164] };
                    #pragma unroll
                    for (int nf = 0; nf < 4; nf++) {
                        int nn = wn * 32 + nf * 8 + g;
                        const float* pb = &SB[0][nn * 20 + kc];
                        float bh0 = pb[0], bh1 = pb[4];
                        const float* pbl = &SB[1][nn * 20 + kc];
                        float bl0 = pbl[0], bl1 = pbl[4];
                        MMA_TF32(c[nf], ah, bh0, bh1);
                        MMA_TF32(c[nf], ah, bl0, bl1);
                        MMA_TF32(c[nf], al, bh0, bh1);
                    }
                }
                __syncthreads();
            }

            const float* pre = g_pre + (size_t)t * BB * NPAD;
            int r0 = m0 + wm * 16 + g;
            int r1 = r0 + 8;
            #pragma unroll
            for (int nf = 0; nf < 4; nf++) {
                int col = n0 + wn * 32 + nf * 8 + 2 * tq;
                float2 p0 = *(const float2*)&pre[(size_t)r0 * NPAD + col];
                float2 p1 = *(const float2*)&pre[(size_t)r1 * NPAD + col];
                float2 v;
                v.x = c[nf][0] + p0.x;
                v.y = c[nf][1] + p0.y;
                *(float2*)&g_xo[r0 * NPAD + col] = v;
                v.x = c[nf][2] + p1.x;
                v.y = c[nf][3] + p1.y;
                *(float2*)&g_xo[r1 * NPAD + col] = v;
            }
        }
        gsync(++phase);

        // ---- phase B: pointwise LSTM update ----
        for (int p = blockIdx.x; p < na; p += GRIDP) {
            const float* xo = g_xo + p * NPAD;
            __syncthreads();
            if (tid == 0) {
                float a0 = xo[0], a1 = xo[1], a2 = xo[2];
                float m = fmaxf(a0, fmaxf(a1, a2));
                float e0 = expf(a0 - m), e1 = expf(a1 - m), e2 = expf(a2 - m);
                float inv = 1.f / (e0 + e1 + e2);
                float fm0 = e0 * inv, fm1 = (e0 + e1) * inv, fm2 = (e0 + e1 + e2) * inv;
                s_fm[0] = fm0; s_fm[1] = fm1; s_fm[2] = fm2;
                float b0 = xo[3], b1 = xo[4], b2 = xo[5];
                float mb = fmaxf(b0, fmaxf(b1, b2));
                float f0 = expf(b0 - mb), f1 = expf(b1 - mb), f2 = expf(b2 - mb);
                float invb = 1.f / (f0 + f1 + f2);
                s_im[0] = (f0 + f1 + f2) * invb; s_im[1] = (f1 + f2) * invb; s_im[2] = f2 * invb;
                g_dish[t * BB + p] = 1.f - (fm0 + fm1 + fm2) * (1.f / 3.f);
            }
            __syncthreads();
            for (int e = tid; e < HH; e += 256) {
                int l = e >> 7;
                float fg = sigm(xo[2 * LL + e]);
                float ig = sigm(xo[2 * LL + HH + e]);
                float og = sigm(xo[2 * LL + 2 * HH + e]);
                float ci = tanhf(xo[2 * LL + 3 * HH + e]);
                float fm = s_fm[l], im = s_im[l], ov = fm * im;
                float cl = g_c[p * HH + e];
                float cn = ov * (fg * cl + ig * ci) + (fm - ov) * cl + (im - ov) * ci;
                float hn = og * tanhf(cn);
                g_c[p * HH + e] = cn;
                g_h[p * HH + e] = hn;
                g_hist[((size_t)t * BB + p) * HH + e] = hn;
            }
        }
        gsync(++phase);
    }
}

// ---------------- batched epilogue ----------------
__global__ void k_fin1(const float* __restrict__ scale_w, const float* __restrict__ scale_b,
                       const float* __restrict__ rescale_w, const float* __restrict__ rescale_b) {
    int p = blockIdx.x;
    int tl = g_vlen[p] - 1;
    int tid = threadIdx.x;
    __shared__ float s_ldis[KW];
    __shared__ float s_th[HH];
    __shared__ float s_r1[HID];

    if (tid == 0) {
        float buf[KW];
        float cs = 0.f;
        #pragma unroll
        for (int k = 0; k < KW; k++) {
            int s = tl - (KW - 1) + k;
            cs += (s >= 0) ? g_dish[s * BB + p] : 0.f;
            buf[k] = cs;
        }
        float m = buf[0];
        #pragma unroll
        for (int k = 1; k < KW; k++) m = fmaxf(m, buf[k]);
        float sum = 0.f;
        #pragma unroll
        for (int k = 0; k < KW; k++) { buf[k] = expf(buf[k] - m); sum += buf[k]; }
        float invs = 1.f / sum;
        #pragma unroll
        for (int k = 0; k < KW; k++) s_ldis[k] = buf[k] * invs;
    }
    __syncthreads();

    for (int e = tid; e < HH; e += 256) {
        float tp = 0.f;
        #pragma unroll
        for (int k = 0; k < KW; k++) {
            int s = tl - (KW - 1) + k;
            float hv = (s >= 0) ? g_hist[((size_t)s * BB + p) * HH + e] : 0.f;
            float lv = hv * s_ldis[k];
            g_lh[(size_t)p * CONVK + e * KW + k] = lv;
            tp += lv;
        }
        s_th[e] = tp * (1.f / KW);
    }
    __syncthreads();

    if (tid < HID) {
        float a = scale_b[tid];
        for (int h = 0; h < HH; h++) a += s_th[h] * scale_w[h * HID + tid];
        s_r1[tid] = fmaxf(a, 0.f);
    }
    __syncthreads();

    for (int e = tid; e < HH; e += 256) {
        float th2 = rescale_b[e];
        #pragma unroll 8
        for (int j = 0; j < HID; j++) th2 += s_r1[j] * rescale_w[j * HH + e];
        g_theme[p * HH + e] = sigm(th2);
    }
}

// fin2: conv GEMM  g_conv[512,384] = g_lh[512,3840] @ g_convT[3840,384]
__global__ void k_fin2() {
    __shared__ float As[16][68];
    __shared__ float Bs[16][68];
    int m0 = blockIdx.y * 64;
    int nb = blockIdx.x * 64;
    int tid  = threadIdx.x;
    int ty   = tid >> 4, tx = tid & 15;
    int arow = tid >> 2, akk = (tid & 3) << 2;
    int bk   = tid >> 4, bn  = (tid & 15) << 2;
    float acc[4][4] = {};
    const float* A = g_lh + (size_t)m0 * CONVK;

    float4 a_nxt = *(const float4*)(A + (size_t)arow * CONVK + akk);
    float4 b_nxt = *(const float4*)(g_convT + bk * HH + nb + bn);

    for (int k0 = 0; k0 < CONVK; k0 += 16) {
        As[akk + 0][arow] = a_nxt.x; As[akk + 1][arow] = a_nxt.y;
        As[akk + 2][arow] = a_nxt.z; As[akk + 3][arow] = a_nxt.w;
        *(float4*)&Bs[bk][bn] = b_nxt;
        __syncthreads();
        if (k0 + 16 < CONVK) {
            a_nxt = *(const float4*)(A + (size_t)arow * CONVK + k0 + 16 + akk);
            b_nxt = *(const float4*)(g_convT + (k0 + 16 + bk) * HH + nb + bn);
        }
        #pragma unroll
        for (int k = 0; k < 16; k++) {
            float4 a = *(const float4*)&As[k][ty * 4];
            float4 b = *(const float4*)&Bs[k][tx * 4];
            float avr[4] = {a.x, a.y, a.z, a.w};
            float bvr[4] = {b.x, b.y, b.z, b.w};
            #pragma unroll
            for (int i = 0; i < 4; i++)
                #pragma unroll
                for (int j = 0; j < 4; j++) acc[i][j] += avr[i] * bvr[j];
        }
        __syncthreads();
    }
    #pragma unroll
    for (int i = 0; i < 4; i++)
        #pragma unroll
        for (int j = 0; j < 4; j++)
            g_conv[(m0 + ty * 4 + i) * HH + nb + tx * 4 + j] = acc[i][j];
}

__global__ void k_fin3(const float* __restrict__ conv_b, const float* __restrict__ out_w,
                       const float* __restrict__ out_b, float* __restrict__ out) {
    int p = blockIdx.x;
    int tid = threadIdx.x;
    int tl = g_vlen[p] - 1;
    __shared__ float s_rnn[HH];
    s_rnn[tid] = g_theme[p * HH + tid] * (g_conv[p * HH + tid] + conv_b[tid])
               + g_hist[((size_t)tl * BB + p) * HH + tid];
    __syncthreads();
    if (tid < LAB) {
        float a = out_b[tid];
        for (int h = 0; h < HH; h++) a += s_rnn[h] * out_w[h * LAB + tid];
        out[g_perm[p] * LAB + tid] = a;
    }
}

// ---------------- launch ----------------
extern "C" void kernel_launch(void* const* d_in, const int* in_sizes, int n_in,
                              void* d_out, int out_size) {
    const float* X         = (const float*)d_in[0];
    const int*   vlen      = (const int*)  d_in[1];
    const float* kw        = (const float*)d_in[2];
    const float* kb        = (const float*)d_in[3];
    const float* rw        = (const float*)d_in[4];
    const float* rb        = (const float*)d_in[5];
    const float* scale_w   = (const float*)d_in[6];
    const float* scale_b   = (const float*)d_in[7];
    const float* rescale_w = (const float*)d_in[8];
    const float* rescale_b = (const float*)d_in[9];
    const float* conv_w    = (const float*)d_in[10];
    const float* conv_b    = (const float*)d_in[11];
    const float* out_w     = (const float*)d_in[12];
    const float* out_b     = (const float*)d_in[13];
    float* out = (float*)d_out;

    k_setup<<<1, 1>>>(vlen);
    k_zero<<<(BB * HH + 255) / 256, 256>>>();
    k_convT<<<(HH * HH * KW + 255) / 256, 256>>>(conv_w);
    k_prep<<<NPAD, 384>>>(kw, kb, rw, rb);

    k_gemm_pre_tf32<<<dim3(13, 1024), 256>>>(X);

    k_loop<<<GRIDP, 256>>>();

    k_fin1<<<BB, 256>>>(scale_w, scale_b, rescale_w, rescale_b);
    k_fin2<<<dim3(HH / 64, BB / 64), 256>>>();
    k_fin3<<<BB, HH>>>(conv_b, out_w, out_b, out);
}

// round 8
// speedup vs baseline: 1.5248x; 1.5248x over previous
#include <cuda_runtime.h>
#include <cuda_fp16.h>

#define BB 512
#define TT 128
#define FF 256
#define HH 384
#define LL 3
#define KW 10
#define LAB 25
#define GATES 1542
#define HID 64
#define CONVK (HH * KW)   // 3840
#define NPAD 1664         // 13*128, 26*64
#define NSTEP_TILES 25    // 25*64 = 1600 >= GATES

// ---------------- device scratch ----------------
__device__ __align__(16) int   g_perm[BB];
__device__ __align__(16) int   g_vlen[BB];
__device__ __align__(16) int   g_nact[TT];
__device__ float g_pre[(size_t)TT * BB * NPAD];               // 436 MB
__device__ float g_xo[BB * NPAD];
__device__ __align__(16) float g_h[BB * HH];
__device__ __align__(16) float g_c[BB * HH];
__device__ __align__(16) float g_hist[(size_t)TT * BB * HH];  // 100 MB
__device__ __align__(16) float g_dish[TT * BB];
__device__ __align__(16) float g_convT[CONVK * HH];
__device__ __align__(16) float g_lh[BB * CONVK];
__device__ __align__(16) float g_theme[BB * HH];
__device__ __align__(16) float g_conv[BB * HH];
// fp16 split weights, transposed to [n][k]
__device__ __align__(16) __half g_BkwH[2][NPAD * FF];         // hi, lo
__device__ __align__(16) __half g_BrwH[2][NPAD * HH];
__device__ __align__(16) float g_bias0[NPAD];
__device__ __align__(16) float g_biasT[NPAD];

__device__ __forceinline__ float sigm(float x) { return 1.f / (1.f + expf(-x)); }

// split two floats into packed half2 hi and lo parts
__device__ __forceinline__ void split2(float x, float y, unsigned& hi, unsigned& lo) {
    __half hx = __float2half_rn(x), hy = __float2half_rn(y);
    __half lx = __float2half_rn(x - __half2float(hx));
    __half ly = __float2half_rn(y - __half2float(hy));
    hi = ((unsigned)__half_as_ushort(hy) << 16) | (unsigned)__half_as_ushort(hx);
    lo = ((unsigned)__half_as_ushort(ly) << 16) | (unsigned)__half_as_ushort(lx);
}

#define MMA_F16(cc, a, b0, b1)                                                  \
    asm volatile("mma.sync.aligned.m16n8k16.row.col.f32.f16.f16.f32 "           \
        "{%0,%1,%2,%3}, {%4,%5,%6,%7}, {%8,%9}, {%0,%1,%2,%3};"                 \
        : "+f"((cc)[0]), "+f"((cc)[1]), "+f"((cc)[2]), "+f"((cc)[3])            \
        : "r"((a)[0]), "r"((a)[1]), "r"((a)[2]), "r"((a)[3]),                   \
          "r"(b0), "r"(b1))

// ---------------- setup ----------------
__global__ void k_setup(const int* __restrict__ vlen) {
    int cnt[129];
    for (int v = 0; v <= 128; v++) cnt[v] = 0;
    for (int b = 0; b < BB; b++) cnt[vlen[b]]++;
    int cur[129];
    int off = 0;
    for (int v = 128; v >= 1; v--) { cur[v] = off; off += cnt[v]; }
    for (int b = 0; b < BB; b++) {
        int v = vlen[b];
        int p = cur[v]++;
        g_perm[p] = b;
        g_vlen[p] = v;
    }
    int suf = 0;
    for (int t = TT - 1; t >= 0; t--) { suf += cnt[t + 1]; g_nact[t] = suf; }
}

__global__ void k_zero() {
    int i = blockIdx.x * blockDim.x + threadIdx.x;
    if (i < BB * HH) { g_h[i] = 0.f; g_c[i] = 0.f; }
}

__global__ void k_convT(const float* __restrict__ cw) {
    int i = blockIdx.x * blockDim.x + threadIdx.x;
    if (i >= HH * HH * KW) return;
    int k  = i % KW;
    int hh = (i / KW) % HH;
    int o  = i / (KW * HH);
    g_convT[(hh * KW + k) * HH + o] = cw[i];
}

// ---------------- prep: split+transpose weights to fp16 hi/lo ----------------
__global__ void k_prep(const float* __restrict__ kw, const float* __restrict__ kb,
                       const float* __restrict__ rw, const float* __restrict__ rb) {
    int n = blockIdx.x;
    int k = threadIdx.x;
    bool v = n < GATES;
    if (k < FF) {
        float w = v ? kw[k * GATES + n] : 0.f;
        __half hi = __float2half_rn(w);
        g_BkwH[0][n * FF + k] = hi;
        g_BkwH[1][n * FF + k] = __float2half_rn(w - __half2float(hi));
    }
    if (k < HH) {
        float w = v ? rw[k * GATES + n] : 0.f;
        __half hi = __float2half_rn(w);
        g_BrwH[0][n * HH + k] = hi;
        g_BrwH[1][n * HH + k] = __float2half_rn(w - __half2float(hi));
    }
    if (k == 0) {
        float b0 = v ? (kb[n] + rb[n]) : 0.f;
        float bT = b0 + (v ? (kw[FF * GATES + n] + rw[HH * GATES + n]) : 0.f);
        g_bias0[n] = b0;
        g_biasT[n] = bT;
    }
}

// ---------------- fp16 pre-GEMM: 64(t) x 128(n) tiles, vlen skip ----------------
// grid (13, 1024): p = by>>1, t0 = (by&1)*64. 256 thr, 8 warps (2wm x 4wn), warp 32x32.
__global__ __launch_bounds__(256) void k_gemm_pre_fp16(const float* __restrict__ X) {
    __shared__ __half SA[2][64 * 24];    // [hi/lo], row stride 24 fp16
    __shared__ __half SB[2][128 * 24];

    int p  = blockIdx.y >> 1;
    int t0 = (blockIdx.y & 1) * 64;
    if (t0 >= g_vlen[p]) return;
    int n0 = blockIdx.x * 128;
    int tid = threadIdx.x;
    int lane = tid & 31, wid = tid >> 5;
    int wm = wid >> 2, wn = wid & 3;
    int g = lane >> 2, tq = lane & 3;
    const float* A = X + (size_t)g_perm[p] * (TT * FF) + (size_t)t0 * FF;

    int am = tid >> 2, ak = (tid & 3) * 4;   // A: 64 rows x 16 fp32, float4 each
    int bm = tid >> 1, bk = (tid & 1) * 8;   // B: 128 rows x 16 fp16, uint4 per layer

    float c[2][4][4] = {};

    float4 va;
    uint4 vbh, vbl;
    va  = *(const float4*)(A + am * FF + ak);
    vbh = *(const uint4*)(&g_BkwH[0][(n0 + bm) * FF + bk]);
    vbl = *(const uint4*)(&g_BkwH[1][(n0 + bm) * FF + bk]);

    const int nK = FF / 16;  // 16
    for (int kt = 0; kt < nK; kt++) {
        {
            unsigned h0, l0, h1, l1;
            split2(va.x, va.y, h0, l0);
            split2(va.z, va.w, h1, l1);
            *(uint2*)&SA[0][am * 24 + ak] = make_uint2(h0, h1);
            *(uint2*)&SA[1][am * 24 + ak] = make_uint2(l0, l1);
            *(uint4*)&SB[0][bm * 24 + bk] = vbh;
            *(uint4*)&SB[1][bm * 24 + bk] = vbl;
        }
        __syncthreads();
        if (kt + 1 < nK) {
            int k0 = (kt + 1) * 16;
            va  = *(const float4*)(A + am * FF + k0 + ak);
            vbh = *(const uint4*)(&g_BkwH[0][(n0 + bm) * FF + k0 + bk]);
            vbl = *(const uint4*)(&g_BkwH[1][(n0 + bm) * FF + k0 + bk]);
        }

        const unsigned* sah = (const unsigned*)SA[0];
        const unsigned* sal = (const unsigned*)SA[1];
        const unsigned* sbh = (const unsigned*)SB[0];
        const unsigned* sbl = (const unsigned*)SB[1];

        unsigned ah[2][4], al[2][4];
        #pragma unroll
        for (int mf = 0; mf < 2; mf++) {
            int r = wm * 32 + mf * 16 + g;       // stride 12 unsigned per row
            ah[mf][0] = sah[r * 12 + tq];
            ah[mf][1] = sah[(r + 8) * 12 + tq];
            ah[mf][2] = sah[r * 12 + tq + 4];
            ah[mf][3] = sah[(r + 8) * 12 + tq + 4];
            al[mf][0] = sal[r * 12 + tq];
            al[mf][1] = sal[(r + 8) * 12 + tq];
            al[mf][2] = sal[r * 12 + tq + 4];
            al[mf][3] = sal[(r + 8) * 12 + tq + 4];
        }
        #pragma unroll
        for (int nf = 0; nf < 4; nf++) {
            int nn = wn * 32 + nf * 8 + g;
            unsigned bh0 = sbh[nn * 12 + tq], bh1 = sbh[nn * 12 + tq + 4];
            unsigned bl0 = sbl[nn * 12 + tq], bl1 = sbl[nn * 12 + tq + 4];
            #pragma unroll
            for (int mf = 0; mf < 2; mf++) {
                MMA_F16(c[mf][nf], ah[mf], bh0, bh1);
                MMA_F16(c[mf][nf], ah[mf], bl0, bl1);
                MMA_F16(c[mf][nf], al[mf], bh0, bh1);
            }
        }
        __syncthreads();
    }

    // epilogue: rows are t = t0 + r
    #pragma unroll
    for (int mf = 0; mf < 2; mf++) {
        int r0 = wm * 32 + mf * 16 + g;
        int r1 = r0 + 8;
        int ta = t0 + r0, tb = t0 + r1;
        #pragma unroll
        for (int nf = 0; nf < 4; nf++) {
            int col = n0 + wn * 32 + nf * 8 + 2 * tq;
            float b0a = (ta == 0) ? g_bias0[col] : g_biasT[col];
            float b0b = (ta == 0) ? g_bias0[col + 1] : g_biasT[col + 1];
            float2 v;
            v.x = c[mf][nf][0] + b0a;
            v.y = c[mf][nf][1] + b0b;
            *(float2*)&g_pre[((size_t)ta * BB + p) * NPAD + col] = v;
            v.x = c[mf][nf][2] + g_biasT[col];
            v.y = c[mf][nf][3] + g_biasT[col + 1];
            *(float2*)&g_pre[((size_t)tb * BB + p) * NPAD + col] = v;
        }
    }
}

// ---------------- fp16 step GEMM: xo = h @ rec_w + PRE[t] ----------------
// 64x64 tile, 128 thr, 4 warps (2x2), warp 32x32
__global__ __launch_bounds__(128) void k_gemm_step_fp16(int t) {
    __shared__ __half SA[2][64 * 24];
    __shared__ __half SB[2][64 * 24];

    int m0 = blockIdx.y * 64;
    if (m0 >= g_nact[t]) return;
    int n0 = blockIdx.x * 64;
    int tid = threadIdx.x;
    int lane = tid & 31, wid = tid >> 5;
    int wm = wid >> 1, wn = wid & 1;
    int g = lane >> 2, tq = lane & 3;

    int am = tid >> 1, ak = (tid & 1) * 8;   // A: 64 rows x 16 fp32, 2x float4
    const float* A = g_h + m0 * HH;

    float c[2][4][4] = {};

    float4 va0, va1;
    uint4 vbh, vbl;
    va0 = *(const float4*)(A + am * HH + ak);
    va1 = *(const float4*)(A + am * HH + ak + 4);
    vbh = *(const uint4*)(&g_BrwH[0][(n0 + am) * HH + ak]);
    vbl = *(const uint4*)(&g_BrwH[1][(n0 + am) * HH + ak]);

    const int nK = HH / 16;  // 24
    for (int kt = 0; kt < nK; kt++) {
        {
            unsigned h0, l0, h1, l1, h2, l2, h3, l3;
            split2(va0.x, va0.y, h0, l0);
            split2(va0.z, va0.w, h1, l1);
            split2(va1.x, va1.y, h2, l2);
            split2(va1.z, va1.w, h3, l3);
            *(uint4*)&SA[0][am * 24 + ak] = make_uint4(h0, h1, h2, h3);
            *(uint4*)&SA[1][am * 24 + ak] = make_uint4(l0, l1, l2, l3);
            *(uint4*)&SB[0][am * 24 + ak] = vbh;
            *(uint4*)&SB[1][am * 24 + ak] = vbl;
        }
        __syncthreads();
        if (kt + 1 < nK) {
            int k0 = (kt + 1) * 16;
            va0 = *(const float4*)(A + am * HH + k0 + ak);
            va1 = *(const float4*)(A + am * HH + k0 + ak + 4);
            vbh = *(const uint4*)(&g_BrwH[0][(n0 + am) * HH + k0 + ak]);
            vbl = *(const uint4*)(&g_BrwH[1][(n0 + am) * HH + k0 + ak]);
        }

        const unsigned* sah = (const unsigned*)SA[0];
        const unsigned* sal = (const unsigned*)SA[1];
        const unsigned* sbh = (const unsigned*)SB[0];
        const unsigned* sbl = (const unsigned*)SB[1];

        unsigned ah[2][4], al[2][4];
        #pragma unroll
        for (int mf = 0; mf < 2; mf++) {
            int r = wm * 32 + mf * 16 + g;
            ah[mf][0] = sah[r * 12 + tq];
            ah[mf][1] = sah[(r + 8) * 12 + tq];
            ah[mf][2] = sah[r * 12 + tq + 4];
            ah[mf][3] = sah[(r + 8) * 12 + tq + 4];
            al[mf][0] = sal[r * 12 + tq];
            al[mf][1] = sal[(r + 8) * 12 + tq];
            al[mf][2] = sal[r * 12 + tq + 4];
            al[mf][3] = sal[(r + 8) * 12 + tq + 4];
        }
        #pragma unroll
        for (int nf = 0; nf < 4; nf++) {
            int nn = wn * 32 + nf * 8 + g;
            unsigned bh0 = sbh[nn * 12 + tq], bh1 = sbh[nn * 12 + tq + 4];
            unsigned bl0 = sbl[nn * 12 + tq], bl1 = sbl[nn * 12 + tq + 4];
            #pragma unroll
            for (int mf = 0; mf < 2; mf++) {
                MMA_F16(c[mf][nf], ah[mf], bh0, bh1);
                MMA_F16(c[mf][nf], ah[mf], bl0, bl1);
                MMA_F16(c[mf][nf], al[mf], bh0, bh1);
            }
        }
        __syncthreads();
    }

    // epilogue: xo = acc + pre[t]
    const float* pre = g_pre + (size_t)t * BB * NPAD;
    #pragma unroll
    for (int mf = 0; mf < 2; mf++) {
        int r0 = m0 + wm * 32 + mf * 16 + g;
        int r1 = r0 + 8;
        #pragma unroll
        for (int nf = 0; nf < 4; nf++) {
            int col = n0 + wn * 32 + nf * 8 + 2 * tq;
            float2 p0 = *(const float2*)&pre[(size_t)r0 * NPAD + col];
            float2 p1 = *(const float2*)&pre[(size_t)r1 * NPAD + col];
            float2 v;
            v.x = c[mf][nf][0] + p0.x;
            v.y = c[mf][nf][1] + p0.y;
            *(float2*)&g_xo[r0 * NPAD + col] = v;
            v.x = c[mf][nf][2] + p1.x;
            v.y = c[mf][nf][3] + p1.y;
            *(float2*)&g_xo[r1 * NPAD + col] = v;
        }
    }
}

// ---------------- per-step pointwise LSTM update ----------------
__global__ void k_point(int t) {
    int p = blockIdx.x;
    if (p >= g_nact[t]) return;
    int tid = threadIdx.x;
    __shared__ float s_fm[LL], s_im[LL];

    const float* xo = g_xo + p * NPAD;
    if (tid == 0) {
        float a0 = xo[0], a1 = xo[1], a2 = xo[2];
        float m = fmaxf(a0, fmaxf(a1, a2));
        float e0 = expf(a0 - m), e1 = expf(a1 - m), e2 = expf(a2 - m);
        float inv = 1.f / (e0 + e1 + e2);
        float fm0 = e0 * inv, fm1 = (e0 + e1) * inv, fm2 = (e0 + e1 + e2) * inv;
        s_fm[0] = fm0; s_fm[1] = fm1; s_fm[2] = fm2;
        float b0 = xo[3], b1 = xo[4], b2 = xo[5];
        float mb = fmaxf(b0, fmaxf(b1, b2));
        float f0 = expf(b0 - mb), f1 = expf(b1 - mb), f2 = expf(b2 - mb);
        float invb = 1.f / (f0 + f1 + f2);
        s_im[0] = (f0 + f1 + f2) * invb; s_im[1] = (f1 + f2) * invb; s_im[2] = f2 * invb;
        g_dish[t * BB + p] = 1.f - (fm0 + fm1 + fm2) * (1.f / 3.f);
    }
    __syncthreads();

    int l = tid >> 7;
    float fg = sigm(xo[2 * LL + tid]);
    float ig = sigm(xo[2 * LL + HH + tid]);
    float og = sigm(xo[2 * LL + 2 * HH + tid]);
    float ci = tanhf(xo[2 * LL + 3 * HH + tid]);
    float fm = s_fm[l], im = s_im[l], ov = fm * im;
    float cl = g_c[p * HH + tid];
    float cn = ov * (fg * cl + ig * ci) + (fm - ov) * cl + (im - ov) * ci;
    float hn = og * tanhf(cn);
    g_c[p * HH + tid] = cn;
    g_h[p * HH + tid] = hn;
    g_hist[((size_t)t * BB + p) * HH + tid] = hn;
}

// ---------------- batched epilogue ----------------
__global__ void k_fin1(const float* __restrict__ scale_w, const float* __restrict__ scale_b,
                       const float* __restrict__ rescale_w, const float* __restrict__ rescale_b) {
    int p = blockIdx.x;
    int tl = g_vlen[p] - 1;
    int tid = threadIdx.x;
    __shared__ float s_ldis[KW];
    __shared__ float s_th[HH];
    __shared__ float s_r1[HID];

    if (tid == 0) {
        float buf[KW];
        float cs = 0.f;
        #pragma unroll
        for (int k = 0; k < KW; k++) {
            int s = tl - (KW - 1) + k;
            cs += (s >= 0) ? g_dish[s * BB + p] : 0.f;
            buf[k] = cs;
        }
        float m = buf[0];
        #pragma unroll
        for (int k = 1; k < KW; k++) m = fmaxf(m, buf[k]);
        float sum = 0.f;
        #pragma unroll
        for (int k = 0; k < KW; k++) { buf[k] = expf(buf[k] - m); sum += buf[k]; }
        float invs = 1.f / sum;
        #pragma unroll
        for (int k = 0; k < KW; k++) s_ldis[k] = buf[k] * invs;
    }
    __syncthreads();

    for (int e = tid; e < HH; e += 256) {
        float tp = 0.f;
        #pragma unroll
        for (int k = 0; k < KW; k++) {
            int s = tl - (KW - 1) + k;
            float hv = (s >= 0) ? g_hist[((size_t)s * BB + p) * HH + e] : 0.f;
            float lv = hv * s_ldis[k];
            g_lh[(size_t)p * CONVK + e * KW + k] = lv;
            tp += lv;
        }
        s_th[e] = tp * (1.f / KW);
    }
    __syncthreads();

    if (tid < HID) {
        float a = scale_b[tid];
        for (int h = 0; h < HH; h++) a += s_th[h] * scale_w[h * HID + tid];
        s_r1[tid] = fmaxf(a, 0.f);
    }
    __syncthreads();

    for (int e = tid; e < HH; e += 256) {
        float th2 = rescale_b[e];
        #pragma unroll 8
        for (int j = 0; j < HID; j++) th2 += s_r1[j] * rescale_w[j * HH + e];
        g_theme[p * HH + e] = sigm(th2);
    }
}

// fin2: conv GEMM  g_conv[512,384] = g_lh[512,3840] @ g_convT[3840,384]
__global__ void k_fin2() {
    __shared__ float As[16][68];
    __shared__ float Bs[16][68];
    int m0 = blockIdx.y * 64;
    int nb = blockIdx.x * 64;
    int tid  = threadIdx.x;
    int ty   = tid >> 4, tx = tid & 15;
    int arow = tid >> 2, akk = (tid & 3) << 2;
    int bk   = tid >> 4, bn  = (tid & 15) << 2;
    float acc[4][4] = {};
    const float* A = g_lh + (size_t)m0 * CONVK;

    float4 a_nxt = *(const float4*)(A + (size_t)arow * CONVK + akk);
    float4 b_nxt = *(const float4*)(g_convT + bk * HH + nb + bn);

    for (int k0 = 0; k0 < CONVK; k0 += 16) {
        As[akk + 0][arow] = a_nxt.x; As[akk + 1][arow] = a_nxt.y;
        As[akk + 2][arow] = a_nxt.z; As[akk + 3][arow] = a_nxt.w;
        *(float4*)&Bs[bk][bn] = b_nxt;
        __syncthreads();
        if (k0 + 16 < CONVK) {
            a_nxt = *(const float4*)(A + (size_t)arow * CONVK + k0 + 16 + akk);
            b_nxt = *(const float4*)(g_convT + (k0 + 16 + bk) * HH + nb + bn);
        }
        #pragma unroll
        for (int k = 0; k < 16; k++) {
            float4 a = *(const float4*)&As[k][ty * 4];
            float4 b = *(const float4*)&Bs[k][tx * 4];
            float avr[4] = {a.x, a.y, a.z, a.w};
            float bvr[4] = {b.x, b.y, b.z, b.w};
            #pragma unroll
            for (int i = 0; i < 4; i++)
                #pragma unroll
                for (int j = 0; j < 4; j++) acc[i][j] += avr[i] * bvr[j];
        }
        __syncthreads();
    }
    #pragma unroll
    for (int i = 0; i < 4; i++)
        #pragma unroll
        for (int j = 0; j < 4; j++)
            g_conv[(m0 + ty * 4 + i) * HH + nb + tx * 4 + j] = acc[i][j];
}

__global__ void k_fin3(const float* __restrict__ conv_b, const float* __restrict__ out_w,
                       const float* __restrict__ out_b, float* __restrict__ out) {
    int p = blockIdx.x;
    int tid = threadIdx.x;
    int tl = g_vlen[p] - 1;
    __shared__ float s_rnn[HH];
    s_rnn[tid] = g_theme[p * HH + tid] * (g_conv[p * HH + tid] + conv_b[tid])
               + g_hist[((size_t)tl * BB + p) * HH + tid];
    __syncthreads();
    if (tid < LAB) {
        float a = out_b[tid];
        for (int h = 0; h < HH; h++) a += s_rnn[h] * out_w[h * LAB + tid];
        out[g_perm[p] * LAB + tid] = a;
    }
}

// ---------------- launch ----------------
extern "C" void kernel_launch(void* const* d_in, const int* in_sizes, int n_in,
                              void* d_out, int out_size) {
    const float* X         = (const float*)d_in[0];
    const int*   vlen      = (const int*)  d_in[1];
    const float* kw        = (const float*)d_in[2];
    const float* kb        = (const float*)d_in[3];
    const float* rw        = (const float*)d_in[4];
    const float* rb        = (const float*)d_in[5];
    const float* scale_w   = (const float*)d_in[6];
    const float* scale_b   = (const float*)d_in[7];
    const float* rescale_w = (const float*)d_in[8];
    const float* rescale_b = (const float*)d_in[9];
    const float* conv_w    = (const float*)d_in[10];
    const float* conv_b    = (const float*)d_in[11];
    const float* out_w     = (const float*)d_in[12];
    const float* out_b     = (const float*)d_in[13];
    float* out = (float*)d_out;

    k_setup<<<1, 1>>>(vlen);
    k_zero<<<(BB * HH + 255) / 256, 256>>>();
    k_convT<<<(HH * HH * KW + 255) / 256, 256>>>(conv_w);
    k_prep<<<NPAD, 384>>>(kw, kb, rw, rb);

    k_gemm_pre_fp16<<<dim3(13, 1024), 256>>>(X);

    for (int t = 0; t < TT; t++) {
        k_gemm_step_fp16<<<dim3(NSTEP_TILES, 8), 128>>>(t);
        k_point<<<BB, HH>>>(t);
    }

    k_fin1<<<BB, 256>>>(scale_w, scale_b, rescale_w, rescale_b);
    k_fin2<<<dim3(HH / 64, BB / 64), 256>>>();
    k_fin3<<<BB, HH>>>(conv_b, out_w, out_b, out);
}